// round 6
// baseline (speedup 1.0000x reference)
#include <cuda_runtime.h>
#include <math.h>
#include <stdint.h>

#define SEQ   4096
#define BATCH 4
#define DIMN  1024
#define NH    16
#define DH    64
#define NL    32
#define WW    8
#define EE    4
#define BAND  16
#define MROWS (BATCH*SEQ)
#define NCH   8
#define CHUNK (SEQ/NCH)

// ---------------- scratch ----------------
__device__ float g_Q [(size_t)BATCH*SEQ*DIMN];
__device__ float g_K [(size_t)BATCH*SEQ*DIMN];
__device__ float g_V [(size_t)BATCH*SEQ*DIMN];
__device__ float g_Ds[(size_t)BATCH*SEQ*NH*NL];   // transposed: (b, c=512, s=4096)
__device__ float g_C [(size_t)BATCH*SEQ*DIMN];
__device__ float g_Kc[(size_t)BATCH*NL*DIMN];
__device__ float g_Vc[(size_t)BATCH*NL*DIMN];
__device__ float g_pK[(size_t)BATCH*NH*NCH*NL*DH];
__device__ float g_pV[(size_t)BATCH*NH*NCH*NL*DH];
__device__ float g_Aq[(size_t)MROWS*DIMN];               // tf32-rounded query
__device__ float g_Wr[(size_t)4*DIMN*DIMN + DIMN*NH*NL]; // tf32-rounded weights

// ---------------- helpers ----------------
__device__ __forceinline__ uint32_t f2tf32(float x) {
    uint32_t u;
    asm("cvt.rna.tf32.f32 %0, %1;" : "=r"(u) : "f"(x));
    return u;
}

__device__ __forceinline__ void mma_tf32(float* c, const uint32_t* a, const uint32_t* b) {
    asm volatile(
        "mma.sync.aligned.m16n8k8.row.col.f32.tf32.tf32.f32 "
        "{%0,%1,%2,%3}, {%4,%5,%6,%7}, {%8,%9}, {%0,%1,%2,%3};"
        : "+f"(c[0]), "+f"(c[1]), "+f"(c[2]), "+f"(c[3])
        : "r"(a[0]), "r"(a[1]), "r"(a[2]), "r"(a[3]), "r"(b[0]), "r"(b[1]));
}

__device__ __forceinline__ void cp_async16(uint32_t dst, const void* src) {
    asm volatile("cp.async.cg.shared.global [%0], [%1], 16;" :: "r"(dst), "l"(src));
}
#define CP_COMMIT() asm volatile("cp.async.commit_group;")
#define CP_WAIT1()  asm volatile("cp.async.wait_group 1;")
#define CP_WAIT0()  asm volatile("cp.async.wait_group 0;")

__device__ __forceinline__ float blk_sum256(float v, float* sh) {
    int t = threadIdx.x;
    #pragma unroll
    for (int o = 16; o; o >>= 1) v += __shfl_xor_sync(0xffffffffu, v, o);
    if ((t & 31) == 0) sh[t >> 5] = v;
    __syncthreads();
    if (t < 32) {
        float x = (t < 8) ? sh[t] : 0.f;
        #pragma unroll
        for (int o = 4; o; o >>= 1) x += __shfl_xor_sync(0xffffffffu, x, o);
        if (t == 0) sh[0] = x;
    }
    __syncthreads();
    float r = sh[0];
    __syncthreads();
    return r;
}

__device__ __forceinline__ float blk_max256(float v, float* sh) {
    int t = threadIdx.x;
    #pragma unroll
    for (int o = 16; o; o >>= 1) v = fmaxf(v, __shfl_xor_sync(0xffffffffu, v, o));
    if ((t & 31) == 0) sh[t >> 5] = v;
    __syncthreads();
    if (t < 32) {
        float x = (t < 8) ? sh[t] : -1e30f;
        #pragma unroll
        for (int o = 4; o; o >>= 1) x = fmaxf(x, __shfl_xor_sync(0xffffffffu, x, o));
        if (t == 0) sh[0] = x;
    }
    __syncthreads();
    float r = sh[0];
    __syncthreads();
    return r;
}

// ---------------- tf32 rounding pass (elementwise) ----------------
__global__ void __launch_bounds__(256)
round_tf32_kernel(const float* __restrict__ src, float* __restrict__ dst, int n4)
{
    int i = blockIdx.x * 256 + threadIdx.x;
    if (i < n4) {
        float4 v = ((const float4*)src)[i];
        v.x = __uint_as_float(f2tf32(v.x));
        v.y = __uint_as_float(f2tf32(v.y));
        v.z = __uint_as_float(f2tf32(v.z));
        v.w = __uint_as_float(f2tf32(v.w));
        ((float4*)dst)[i] = v;
    }
}

// ---------------- tf32 tensor-core GEMM (inputs pre-rounded to tf32) ----------------
// out = alpha*(A@W + bias). A is (16384 x 1024). K fixed = 1024.
// remap_in:  A row m=(b*S+s) lives at A[(s*B+b)*1024]
// remap_out: 0 = direct (m,N); 1 = transpose rows to (s*B+b); 2 = D-transpose (b, col, s)
#define BM 128
#define BN 128
#define BKK 32
#define ASTRIDE 36
#define BSTRIDE 136
#define A_FLOATS (BM*ASTRIDE)                 // 4608
#define STAGE_FLOATS (A_FLOATS + BKK*BSTRIDE) // 8960
#define STAGE_BYTES (STAGE_FLOATS*4)          // 35840
#define GEMM_SMEM (2*STAGE_BYTES)             // 71680

__global__ void __launch_bounds__(256, 2)
gemm_tf32(const float* __restrict__ A, const float* __restrict__ Wt,
          const float* __restrict__ bias, float* __restrict__ out,
          int N, float alpha, int remap_in, int remap_out)
{
    extern __shared__ float smem[];
    const uint32_t smem_u32 = (uint32_t)__cvta_generic_to_shared(smem);
    const int t  = threadIdx.x;
    const int bx = blockIdx.x, by = blockIdx.y;
    const int lane = t & 31;
    const int warp = t >> 5;
    const int wm = (warp & 1) * 64;   // 2 warps in M
    const int wn = (warp >> 1) * 32;  // 4 warps in N

    // ---- load-phase thread mapping ----
    const int lar = t >> 3;          // A row lane 0..31
    const int lac = (t & 7) * 4;     // A col (floats)
    const float* aSrc[4];
    uint32_t aOff[4];
    #pragma unroll
    for (int i = 0; i < 4; i++) {
        int m = by * BM + lar + i * 32;
        size_t arow = remap_in ? ((size_t)(m & (SEQ-1)) * BATCH + (m >> 12)) : (size_t)m;
        aSrc[i] = A + arow * DIMN + lac;
        aOff[i] = (uint32_t)(((lar + i * 32) * ASTRIDE + lac) * 4);
    }
    const int lbr = t >> 5;          // B k-row 0..7
    const int lbc = (t & 31) * 4;    // B col (floats)
    const float* bSrc = Wt + (size_t)lbr * N + bx * BN + lbc;
    uint32_t bOff[4];
    #pragma unroll
    for (int i = 0; i < 4; i++)
        bOff[i] = (uint32_t)(A_FLOATS * 4 + ((lbr + i * 8) * BSTRIDE + lbc) * 4);

    float acc[4][4][4];
    #pragma unroll
    for (int mi = 0; mi < 4; mi++)
        #pragma unroll
        for (int ni = 0; ni < 4; ni++)
            #pragma unroll
            for (int r = 0; r < 4; r++) acc[mi][ni][r] = 0.f;

    // ---- prologue: stages 0, 1 ----
    #pragma unroll
    for (int s = 0; s < 2; s++) {
        uint32_t sb = smem_u32 + s * STAGE_BYTES;
        int k0 = s * BKK;
        #pragma unroll
        for (int i = 0; i < 4; i++) cp_async16(sb + aOff[i], aSrc[i] + k0);
        #pragma unroll
        for (int i = 0; i < 4; i++) cp_async16(sb + bOff[i], bSrc + (size_t)(k0 + i * 8) * N);
        CP_COMMIT();
    }

    const int NKT = DIMN / BKK;   // 32
    #pragma unroll 1
    for (int kt = 0; kt < NKT; kt++) {
        if (kt < NKT - 1) { CP_WAIT1(); } else { CP_WAIT0(); }
        __syncthreads();

        const float* As = smem + (kt & 1) * STAGE_FLOATS;
        const float* Bs = As + A_FLOATS;

        #pragma unroll
        for (int ks = 0; ks < 4; ks++) {
            const int kk = ks * 8;
            uint32_t af[4][4], bf[4][2];
            #pragma unroll
            for (int mi = 0; mi < 4; mi++) {
                const float* ar = As + (wm + mi * 16 + (lane >> 2)) * ASTRIDE + kk + (lane & 3);
                af[mi][0] = __float_as_uint(ar[0]);
                af[mi][1] = __float_as_uint(ar[8 * ASTRIDE]);
                af[mi][2] = __float_as_uint(ar[4]);
                af[mi][3] = __float_as_uint(ar[8 * ASTRIDE + 4]);
            }
            #pragma unroll
            for (int ni = 0; ni < 4; ni++) {
                const float* br = Bs + (kk + (lane & 3)) * BSTRIDE + wn + ni * 8 + (lane >> 2);
                bf[ni][0] = __float_as_uint(br[0]);
                bf[ni][1] = __float_as_uint(br[4 * BSTRIDE]);
            }
            #pragma unroll
            for (int mi = 0; mi < 4; mi++)
                #pragma unroll
                for (int ni = 0; ni < 4; ni++)
                    mma_tf32(acc[mi][ni], af[mi], bf[ni]);
        }

        __syncthreads();
        if (kt < NKT - 2) {
            uint32_t sb = smem_u32 + (kt & 1) * STAGE_BYTES;
            int k0 = (kt + 2) * BKK;
            #pragma unroll
            for (int i = 0; i < 4; i++) cp_async16(sb + aOff[i], aSrc[i] + k0);
            #pragma unroll
            for (int i = 0; i < 4; i++) cp_async16(sb + bOff[i], bSrc + (size_t)(k0 + i * 8) * N);
            CP_COMMIT();
        }
    }

    // ---- epilogue ----
    #pragma unroll
    for (int ni = 0; ni < 4; ni++) {
        int col = bx * BN + wn + ni * 8 + 2 * (lane & 3);
        float bv0 = bias[col], bv1 = bias[col + 1];
        #pragma unroll
        for (int mi = 0; mi < 4; mi++) {
            const float* a = acc[mi][ni];
            int m0 = by * BM + wm + mi * 16 + (lane >> 2);
            int m1 = m0 + 8;
            float o00 = alpha * (a[0] + bv0), o01 = alpha * (a[1] + bv1);
            float o10 = alpha * (a[2] + bv0), o11 = alpha * (a[3] + bv1);
            if (remap_out == 2) {
                out[((size_t)((m0 >> 12) * (NH*NL) + col    )) * SEQ + (m0 & (SEQ-1))] = o00;
                out[((size_t)((m0 >> 12) * (NH*NL) + col + 1)) * SEQ + (m0 & (SEQ-1))] = o01;
                out[((size_t)((m1 >> 12) * (NH*NL) + col    )) * SEQ + (m1 & (SEQ-1))] = o10;
                out[((size_t)((m1 >> 12) * (NH*NL) + col + 1)) * SEQ + (m1 & (SEQ-1))] = o11;
            } else {
                size_t r0 = remap_out ? ((size_t)(m0 & (SEQ-1)) * BATCH + (m0 >> 12)) : (size_t)m0;
                size_t r1 = remap_out ? ((size_t)(m1 & (SEQ-1)) * BATCH + (m1 >> 12)) : (size_t)m1;
                float2 v0 = make_float2(o00, o01);
                float2 v1 = make_float2(o10, o11);
                *(float2*)(out + r0 * N + col) = v0;
                *(float2*)(out + r1 * N + col) = v1;
            }
        }
    }
}

// ---------------- layernorm over last dim (1024), in place ----------------
__global__ void __launch_bounds__(256)
ln_kernel(float* __restrict__ data, const float* __restrict__ gamma,
          const float* __restrict__ beta)
{
    __shared__ float sh[32];
    const size_t row = blockIdx.x;
    float* p = data + row * DIMN;
    const int t = threadIdx.x;
    float4 v = ((const float4*)p)[t];
    float s = v.x + v.y + v.z + v.w;
    float mean = blk_sum256(s, sh) * (1.f / DIMN);
    float4 dx = {v.x - mean, v.y - mean, v.z - mean, v.w - mean};
    float sq = dx.x*dx.x + dx.y*dx.y + dx.z*dx.z + dx.w*dx.w;
    float var = blk_sum256(sq, sh) * (1.f / DIMN);
    float rstd = rsqrtf(var + 1e-5f);
    float4 g4 = ((const float4*)gamma)[t];
    float4 b4 = ((const float4*)beta)[t];
    float4 o4;
    o4.x = dx.x * rstd * g4.x + b4.x;
    o4.y = dx.y * rstd * g4.y + b4.y;
    o4.z = dx.z * rstd * g4.z + b4.z;
    o4.w = dx.w * rstd * g4.w + b4.w;
    ((float4*)p)[t] = o4;
}

// ---------------- softmax over contiguous rows of Dt (b*512 rows of 4096) ----------------
__global__ void __launch_bounds__(256)
dsoftmax_kernel(float* __restrict__ Dt)
{
    __shared__ float sh[32];
    float* p = Dt + (size_t)blockIdx.x * SEQ;
    const int t = threadIdx.x;
    float4 v[4];
    float mx = -1e30f;
    #pragma unroll
    for (int i = 0; i < 4; i++) {
        v[i] = ((const float4*)p)[t + i * 256];
        mx = fmaxf(mx, fmaxf(fmaxf(v[i].x, v[i].y), fmaxf(v[i].z, v[i].w)));
    }
    mx = blk_max256(mx, sh);
    float sum = 0.f;
    #pragma unroll
    for (int i = 0; i < 4; i++) {
        v[i].x = expf(v[i].x - mx); v[i].y = expf(v[i].y - mx);
        v[i].z = expf(v[i].z - mx); v[i].w = expf(v[i].w - mx);
        sum += v[i].x + v[i].y + v[i].z + v[i].w;
    }
    sum = blk_sum256(sum, sh);
    float inv = 1.f / sum;
    #pragma unroll
    for (int i = 0; i < 4; i++) {
        v[i].x *= inv; v[i].y *= inv; v[i].z *= inv; v[i].w *= inv;
        ((float4*)p)[t + i * 256] = v[i];
    }
}

// ---------------- compression partials: Kc/Vc = hs @ K/V over an s-chunk ----------------
// Dt layout (b, c=h*32+l, s)
__global__ void __launch_bounds__(256)
compress_kernel(const float* __restrict__ Dt, const float* __restrict__ K,
                const float* __restrict__ V,
                float* __restrict__ partK, float* __restrict__ partV)
{
    const int bh = blockIdx.x;         // 0..63
    const int chunk = blockIdx.y;      // 0..NCH-1
    const int b = bh >> 4, h = bh & 15;
    const int t = threadIdx.x;
    const int d = t & 63;
    const int lbase = (t >> 6) * 8;

    __shared__ float sh_hs[NL][36];    // [l][si]
    __shared__ float sh_K[32][64];
    __shared__ float sh_V[32][64];

    float accK[8], accV[8];
    #pragma unroll
    for (int i = 0; i < 8; i++) { accK[i] = 0.f; accV[i] = 0.f; }

    const int lrow = t >> 3;           // 0..31
    const int s4   = (t & 7) * 4;
    const float* dtrow = Dt + ((size_t)(b * (NH*NL) + h * NL + lrow)) * SEQ;
    const int kvr = t >> 4;            // 0..15
    const int d4  = (t & 15) * 4;

    const int s0c = chunk * CHUNK;
    for (int stage = 0; stage < CHUNK / 32; stage++) {
        const int sbase = s0c + stage * 32;
        __syncthreads();
        float4 hv = *(const float4*)(dtrow + sbase + s4);
        *(float4*)&sh_hs[lrow][s4] = hv;
        #pragma unroll
        for (int i = 0; i < 2; i++) {
            int si = kvr + i * 16;
            size_t src = ((size_t)(b * SEQ + sbase + si)) * DIMN + h * DH + d4;
            *(float4*)&sh_K[si][d4] = *(const float4*)(K + src);
            *(float4*)&sh_V[si][d4] = *(const float4*)(V + src);
        }
        __syncthreads();
        #pragma unroll 4
        for (int si = 0; si < 32; si++) {
            float kv = sh_K[si][d], vv = sh_V[si][d];
            #pragma unroll
            for (int li = 0; li < 8; li++) {
                float hsv = sh_hs[lbase + li][si];
                accK[li] = fmaf(hsv, kv, accK[li]);
                accV[li] = fmaf(hsv, vv, accV[li]);
            }
        }
    }
    #pragma unroll
    for (int li = 0; li < 8; li++) {
        size_t idx = (((size_t)bh * NCH + chunk) * NL + lbase + li) * DH + d;
        partK[idx] = accK[li];
        partV[idx] = accV[li];
    }
}

// ---------------- reduce partials -> Kc/Vc laid out (b, l, h*64+d) ----------------
__global__ void __launch_bounds__(256)
reduce_kc(const float* __restrict__ partK, const float* __restrict__ partV,
          float* __restrict__ Kc, float* __restrict__ Vc)
{
    const int e = blockIdx.x * 256 + threadIdx.x;
    const int d = e & 63;
    const int h = (e >> 6) & 15;
    const int l = (e >> 10) & 31;
    const int b = e >> 15;
    const int bh = b * NH + h;
    float sK = 0.f, sV = 0.f;
    #pragma unroll
    for (int c = 0; c < NCH; c++) {
        size_t idx = (((size_t)bh * NCH + c) * NL + l) * DH + d;
        sK += partK[idx];
        sV += partV[idx];
    }
    size_t o = ((size_t)(b * NL + l)) * DIMN + h * DH + d;
    Kc[o] = sK;
    Vc[o] = sV;
}

// ---------------- fused attention (compressed 32 keys + window 16 keys) ----------------
#define GPB 2
#define NQ  (GPB*WW)               // 16 queries per block
#define NWK ((GPB-1)*WW + BAND)    // 24 window rows

__global__ void __launch_bounds__(256)
attn_kernel(const float* __restrict__ Q, const float* __restrict__ K,
            const float* __restrict__ V, const float* __restrict__ Kc,
            const float* __restrict__ Vc, float* __restrict__ C)
{
    const int gblk = blockIdx.x;
    const int h = blockIdx.y;
    const int b = blockIdx.z;
    const int s0  = gblk * NQ;
    const int wk0 = s0 - EE;

    __shared__ float sKc[NL][68];
    __shared__ float sVc[NL][68];
    __shared__ float sKw[NWK][68];
    __shared__ float sVw[NWK][68];
    __shared__ float sQ [NQ][68];
    __shared__ float sp [NQ][48];

    const int t = threadIdx.x;

    for (int i = t; i < NL * DH; i += 256) {
        int l = i >> 6, d = i & 63;
        size_t src = ((size_t)(b * NL + l)) * DIMN + h * DH + d;
        sKc[l][d] = Kc[src];
        sVc[l][d] = Vc[src];
    }
    for (int i = t; i < NQ * DH; i += 256) {
        int q = i >> 6, d = i & 63;
        sQ[q][d] = Q[((size_t)(b * SEQ + s0 + q)) * DIMN + h * DH + d];
    }
    for (int i = t; i < NWK * DH; i += 256) {
        int r = i >> 6, d = i & 63;
        int sk = wk0 + r;
        float kv = 0.f, vv = 0.f;
        if (sk >= 0 && sk < SEQ) {
            size_t src = ((size_t)(b * SEQ + sk)) * DIMN + h * DH + d;
            kv = K[src]; vv = V[src];
        }
        sKw[r][d] = kv;
        sVw[r][d] = vv;
    }
    __syncthreads();

    const int warp = t >> 5, lane = t & 31;
    #pragma unroll
    for (int qq = 0; qq < 2; qq++) {
        const int q = warp * 2 + qq;
        const int grp = q >> 3;
        const int woff = grp * WW;
        const float* qrow  = sQ[q];
        const float* krow0 = sKc[lane];
        const float* krow1 = sKw[woff + (lane & 15)];
        float sc0 = 0.f, sc1 = 0.f;
        #pragma unroll
        for (int dd = 0; dd < DH; dd += 4) {
            float4 qa = *(const float4*)(qrow + dd);
            float4 ka = *(const float4*)(krow0 + dd);
            float4 kb = *(const float4*)(krow1 + dd);
            sc0 += qa.x*ka.x + qa.y*ka.y + qa.z*ka.z + qa.w*ka.w;
            sc1 += qa.x*kb.x + qa.y*kb.y + qa.z*kb.z + qa.w*kb.w;
        }
        bool wvalid = (lane < 16);
        if (wvalid) {
            int sk = wk0 + woff + lane;
            if (sk < 0 || sk >= SEQ) wvalid = false;
        }
        float swin = wvalid ? sc1 : -1e30f;
        float m = fmaxf(sc0, swin);
        #pragma unroll
        for (int o = 16; o; o >>= 1) m = fmaxf(m, __shfl_xor_sync(0xffffffffu, m, o));
        float e0 = expf(sc0 - m);
        float e1 = wvalid ? expf(swin - m) : 0.f;
        float ssum = e0 + e1;
        #pragma unroll
        for (int o = 16; o; o >>= 1) ssum += __shfl_xor_sync(0xffffffffu, ssum, o);
        float inv = 1.f / ssum;
        sp[q][lane] = e0 * inv;
        if (lane < 16) sp[q][32 + lane] = e1 * inv;
    }
    __syncthreads();

    for (int i = t; i < NQ * DH; i += 256) {
        int q = i >> 6, d = i & 63;
        int woff = (q >> 3) * WW;
        float acc = 0.f;
        #pragma unroll
        for (int l = 0; l < NL; l++) acc = fmaf(sp[q][l], sVc[l][d], acc);
        #pragma unroll
        for (int j = 0; j < BAND; j++) acc = fmaf(sp[q][32 + j], sVw[woff + j][d], acc);
        // pre-round to tf32 so the Wo GEMM can skip conversion
        C[((size_t)(b * SEQ + s0 + q)) * DIMN + h * DH + d] = __uint_as_float(f2tf32(acc));
    }
}

// ---------------- launch ----------------
extern "C" void kernel_launch(void* const* d_in, const int* in_sizes, int n_in,
                              void* d_out, int out_size)
{
    const float* query = (const float*)d_in[0];
    const float* Wq  = (const float*)d_in[1];
    const float* bq  = (const float*)d_in[2];
    const float* Wk  = (const float*)d_in[3];
    const float* bk  = (const float*)d_in[4];
    const float* Wv  = (const float*)d_in[5];
    const float* bv  = (const float*)d_in[6];
    const float* Wo  = (const float*)d_in[7];
    const float* bo  = (const float*)d_in[8];
    const float* g_l = (const float*)d_in[9];
    const float* b_l = (const float*)d_in[10];
    const float* g_s = (const float*)d_in[11];
    const float* b_s = (const float*)d_in[12];
    const float* Wd  = (const float*)d_in[13];
    const float* bd  = (const float*)d_in[14];
    float* out = (float*)d_out;

    float *Qb, *Kb, *Vb, *Db, *Cb, *Kcb, *Vcb, *pK, *pV, *Aq, *Wr;
    cudaGetSymbolAddress((void**)&Qb,  g_Q);
    cudaGetSymbolAddress((void**)&Kb,  g_K);
    cudaGetSymbolAddress((void**)&Vb,  g_V);
    cudaGetSymbolAddress((void**)&Db,  g_Ds);
    cudaGetSymbolAddress((void**)&Cb,  g_C);
    cudaGetSymbolAddress((void**)&Kcb, g_Kc);
    cudaGetSymbolAddress((void**)&Vcb, g_Vc);
    cudaGetSymbolAddress((void**)&pK,  g_pK);
    cudaGetSymbolAddress((void**)&pV,  g_pV);
    cudaGetSymbolAddress((void**)&Aq,  g_Aq);
    cudaGetSymbolAddress((void**)&Wr,  g_Wr);

    static int smem_set = 0;
    if (!smem_set) {
        cudaFuncSetAttribute(gemm_tf32, cudaFuncAttributeMaxDynamicSharedMemorySize, GEMM_SMEM);
        smem_set = 1;
    }

    const size_t WSZ = (size_t)DIMN * DIMN;        // 1048576
    float* rWq = Wr;
    float* rWk = Wr + WSZ;
    float* rWv = Wr + 2 * WSZ;
    float* rWo = Wr + 3 * WSZ;
    float* rWd = Wr + 4 * WSZ;

    // tf32 rounding passes (once; amortized over all GEMMs)
    round_tf32_kernel<<<(MROWS*DIMN/4 + 255)/256, 256>>>(query, Aq, MROWS*DIMN/4);
    round_tf32_kernel<<<(int)(WSZ/4 + 255)/256, 256>>>(Wq, rWq, (int)(WSZ/4));
    round_tf32_kernel<<<(int)(WSZ/4 + 255)/256, 256>>>(Wk, rWk, (int)(WSZ/4));
    round_tf32_kernel<<<(int)(WSZ/4 + 255)/256, 256>>>(Wv, rWv, (int)(WSZ/4));
    round_tf32_kernel<<<(int)(WSZ/4 + 255)/256, 256>>>(Wo, rWo, (int)(WSZ/4));
    round_tf32_kernel<<<(DIMN*NH*NL/4 + 255)/256, 256>>>(Wd, rWd, DIMN*NH*NL/4);

    // Projections (tf32 tensor cores, pre-rounded inputs)
    gemm_tf32<<<dim3(8, 128), 256, GEMM_SMEM>>>(Aq, rWq, bq, Qb, 1024, 0.125f, 1, 0);
    gemm_tf32<<<dim3(8, 128), 256, GEMM_SMEM>>>(Aq, rWk, bk, Kb, 1024, 1.0f,   1, 0);
    gemm_tf32<<<dim3(8, 128), 256, GEMM_SMEM>>>(Aq, rWv, bv, Vb, 1024, 1.0f,   1, 0);
    gemm_tf32<<<dim3(4, 128), 256, GEMM_SMEM>>>(Aq, rWd, bd, Db,  512, 1.0f,   1, 2);

    // LayerNorm on K, V
    ln_kernel<<<MROWS, 256>>>(Kb, g_l, b_l);
    ln_kernel<<<MROWS, 256>>>(Vb, g_l, b_l);

    // head_scores softmax over sequence axis (contiguous rows of Dt)
    dsoftmax_kernel<<<BATCH * NH * NL, 256>>>(Db);

    // Compression
    compress_kernel<<<dim3(BATCH * NH, NCH), 256>>>(Db, Kb, Vb, pK, pV);
    reduce_kc<<<(BATCH * NL * DIMN) / 256, 256>>>(pK, pV, Kcb, Vcb);

    // LayerNorm on compressed K/V
    ln_kernel<<<BATCH * NL, 256>>>(Kcb, g_s, b_s);
    ln_kernel<<<BATCH * NL, 256>>>(Vcb, g_s, b_s);

    // Fused long-short attention (writes tf32-rounded C)
    attn_kernel<<<dim3(SEQ / NQ, NH, BATCH), 256>>>(Qb, Kb, Vb, Kcb, Vcb, Cb);

    // Output projection with transposed write to (s, b, DIM)
    gemm_tf32<<<dim3(8, 128), 256, GEMM_SMEM>>>(Cb, rWo, bo, out, 1024, 1.0f, 0, 1);
}

// round 11
// speedup vs baseline: 1.4157x; 1.4157x over previous
#include <cuda_runtime.h>
#include <cuda_fp16.h>
#include <math.h>
#include <stdint.h>

#define SEQ   4096
#define BATCH 4
#define DIMN  1024
#define NH    16
#define DH    64
#define NL    32
#define WW    8
#define EE    4
#define BAND  16
#define MROWS (BATCH*SEQ)
#define NCH   8
#define CHUNK (SEQ/NCH)

// ---------------- scratch ----------------
__device__ float  g_Q [(size_t)BATCH*SEQ*DIMN];
__device__ float  g_K [(size_t)BATCH*SEQ*DIMN];
__device__ float  g_V [(size_t)BATCH*SEQ*DIMN];
__device__ float  g_Ds[(size_t)BATCH*SEQ*NH*NL];   // transposed: (b, c=512, s=4096)
__device__ float  g_Kc[(size_t)BATCH*NL*DIMN];
__device__ float  g_Vc[(size_t)BATCH*NL*DIMN];
__device__ float  g_pK[(size_t)BATCH*NH*NCH*NL*DH];
__device__ float  g_pV[(size_t)BATCH*NH*NCH*NL*DH];
__device__ __half g_Ah[(size_t)MROWS*DIMN];                // fp16 query
__device__ __half g_Wh[(size_t)4*DIMN*DIMN + DIMN*NH*NL];  // fp16 transposed weights [n][k]
__device__ __half g_Ch[(size_t)BATCH*SEQ*DIMN];            // fp16 attention output

// ---------------- PTX helpers ----------------
__device__ __forceinline__ void mma_f16(float* c, const uint32_t* a, uint32_t b0, uint32_t b1) {
    asm volatile(
        "mma.sync.aligned.m16n8k16.row.col.f32.f16.f16.f32 "
        "{%0,%1,%2,%3}, {%4,%5,%6,%7}, {%8,%9}, {%0,%1,%2,%3};"
        : "+f"(c[0]), "+f"(c[1]), "+f"(c[2]), "+f"(c[3])
        : "r"(a[0]), "r"(a[1]), "r"(a[2]), "r"(a[3]), "r"(b0), "r"(b1));
}

__device__ __forceinline__ void ldsm_x4(uint32_t* r, uint32_t addr) {
    asm volatile("ldmatrix.sync.aligned.m8n8.x4.shared.b16 {%0,%1,%2,%3}, [%4];"
        : "=r"(r[0]), "=r"(r[1]), "=r"(r[2]), "=r"(r[3]) : "r"(addr));
}

__device__ __forceinline__ void cp_async16(uint32_t dst, const void* src) {
    asm volatile("cp.async.cg.shared.global [%0], [%1], 16;" :: "r"(dst), "l"(src));
}
#define CP_COMMIT() asm volatile("cp.async.commit_group;")
#define CP_WAIT2()  asm volatile("cp.async.wait_group 2;")
#define CP_WAIT1()  asm volatile("cp.async.wait_group 1;")
#define CP_WAIT0()  asm volatile("cp.async.wait_group 0;")

// ---------------- block reductions ----------------
__device__ __forceinline__ float blk_sum256(float v, float* sh) {
    int t = threadIdx.x;
    #pragma unroll
    for (int o = 16; o; o >>= 1) v += __shfl_xor_sync(0xffffffffu, v, o);
    if ((t & 31) == 0) sh[t >> 5] = v;
    __syncthreads();
    if (t < 32) {
        float x = (t < 8) ? sh[t] : 0.f;
        #pragma unroll
        for (int o = 4; o; o >>= 1) x += __shfl_xor_sync(0xffffffffu, x, o);
        if (t == 0) sh[0] = x;
    }
    __syncthreads();
    float r = sh[0];
    __syncthreads();
    return r;
}

__device__ __forceinline__ float blk_max256(float v, float* sh) {
    int t = threadIdx.x;
    #pragma unroll
    for (int o = 16; o; o >>= 1) v = fmaxf(v, __shfl_xor_sync(0xffffffffu, v, o));
    if ((t & 31) == 0) sh[t >> 5] = v;
    __syncthreads();
    if (t < 32) {
        float x = (t < 8) ? sh[t] : -1e30f;
        #pragma unroll
        for (int o = 4; o; o >>= 1) x = fmaxf(x, __shfl_xor_sync(0xffffffffu, x, o));
        if (t == 0) sh[0] = x;
    }
    __syncthreads();
    float r = sh[0];
    __syncthreads();
    return r;
}

// ---------------- fp16 conversion passes ----------------
__global__ void __launch_bounds__(256)
convert_half_kernel(const float* __restrict__ src, __half* __restrict__ dst, int n4)
{
    int i = blockIdx.x * 256 + threadIdx.x;
    if (i < n4) {
        float4 v = ((const float4*)src)[i];
        __half2 h0 = __floats2half2_rn(v.x, v.y);
        __half2 h1 = __floats2half2_rn(v.z, v.w);
        ((__half2*)dst)[2*i]   = h0;
        ((__half2*)dst)[2*i+1] = h1;
    }
}

// src [R][C] f32 -> dst [C][R] f16
__global__ void __launch_bounds__(256)
transpose_half_kernel(const float* __restrict__ src, __half* __restrict__ dst,
                      int R, int C)
{
    __shared__ float tl[32][33];
    const int tx = threadIdx.x & 31, ty = threadIdx.x >> 5;   // 32x8
    const int c0 = blockIdx.x * 32, r0 = blockIdx.y * 32;
    #pragma unroll
    for (int j = 0; j < 4; j++)
        tl[ty + j * 8][tx] = src[(size_t)(r0 + ty + j * 8) * C + c0 + tx];
    __syncthreads();
    #pragma unroll
    for (int j = 0; j < 4; j++)
        dst[(size_t)(c0 + ty + j * 8) * R + r0 + tx] =
            __float2half_rn(tl[tx][ty + j * 8]);
}

// ---------------- fp16 tensor-core GEMM ----------------
// out = alpha*(A@W + bias). A fp16 (16384 x 1024); Wt fp16 [N][1024] K-major.
// remap_in: A row m=(b*S+s) at A[(s*B+b)]; remap_out: 0 direct, 1 transpose rows, 2 D-transpose.
#define BM 128
#define BN 128
#define BKH 32                    // halfs of K per stage (64B rows)
#define NKT (DIMN/BKH)            // 32
#define ABYTES (BM*BKH*2)         // 8192
#define STGB  (2*ABYTES)          // 16384 (A + B)
#define GEMM_SMEM (4*STGB)        // 65536, 4-stage ring

__global__ void __launch_bounds__(256, 2)
gemm_fp16(const __half* __restrict__ A, const __half* __restrict__ Wt,
          const float* __restrict__ bias, float* __restrict__ out,
          int N, float alpha, int remap_in, int remap_out)
{
    extern __shared__ __half smh[];
    const uint32_t smem_u32 = (uint32_t)__cvta_generic_to_shared(smh);
    const int t = threadIdx.x;
    const int bx = blockIdx.x, by = blockIdx.y;
    const int lane = t & 31, warp = t >> 5;
    const int wm = (warp & 1) * 64;    // 2 warps in M
    const int wn = (warp >> 1) * 32;   // 4 warps in N

    // ---- cp.async mapping: A/B stages are 128 rows x 32 halfs (64B rows, 4x16B chunks)
    // swizzle: chunk_swz = c ^ ((row>>1)&3)  (conflict-free for ldmatrix AND cp.async)
    const __half* aSrc[2]; uint32_t aOff[2];
    const __half* bSrc[2]; uint32_t bOff[2];
    #pragma unroll
    for (int i = 0; i < 2; i++) {
        int idx = t + i * 256;          // 0..511
        int row = idx >> 2, c = idx & 3;
        int m = by * BM + row;
        size_t arow = remap_in ? ((size_t)(m & (SEQ-1)) * BATCH + (m >> 12)) : (size_t)m;
        aSrc[i] = A + arow * DIMN + c * 8;
        aOff[i] = (uint32_t)(row * 64 + ((c ^ ((row >> 1) & 3)) * 16));
        int n = bx * BN + row;
        bSrc[i] = Wt + (size_t)n * DIMN + c * 8;
        bOff[i] = (uint32_t)(ABYTES + row * 64 + ((c ^ ((row >> 1) & 3)) * 16));
    }

    float acc[4][4][4];
    #pragma unroll
    for (int mi = 0; mi < 4; mi++)
        #pragma unroll
        for (int ni = 0; ni < 4; ni++)
            #pragma unroll
            for (int r = 0; r < 4; r++) acc[mi][ni][r] = 0.f;

    // ---- prologue: stages 0..2 ----
    #pragma unroll
    for (int s = 0; s < 3; s++) {
        uint32_t sb = smem_u32 + s * STGB;
        int k0 = s * BKH;
        #pragma unroll
        for (int i = 0; i < 2; i++) cp_async16(sb + aOff[i], aSrc[i] + k0);
        #pragma unroll
        for (int i = 0; i < 2; i++) cp_async16(sb + bOff[i], bSrc[i] + k0);
        CP_COMMIT();
    }

    const int r15 = lane & 15;
    const int chi = lane >> 4;
    const int swx = (r15 >> 1) & 3;

    #pragma unroll 1
    for (int kt = 0; kt < NKT; kt++) {
        if (kt < NKT - 2)       { CP_WAIT2(); }
        else if (kt == NKT - 2) { CP_WAIT1(); }
        else                    { CP_WAIT0(); }
        __syncthreads();

        uint32_t sA = smem_u32 + (kt & 3) * STGB;
        uint32_t sB = sA + ABYTES;

        #pragma unroll
        for (int kb = 0; kb < 2; kb++) {
            uint32_t a[4][4], b2[2][4];
            uint32_t sw = (uint32_t)((((kb * 2 + chi) ^ swx) & 3) * 16);
            #pragma unroll
            for (int mi = 0; mi < 4; mi++)
                ldsm_x4(a[mi], sA + (wm + mi * 16 + r15) * 64 + sw);
            #pragma unroll
            for (int nh = 0; nh < 2; nh++)
                ldsm_x4(b2[nh], sB + (wn + nh * 16 + r15) * 64 + sw);
            #pragma unroll
            for (int mi = 0; mi < 4; mi++)
                #pragma unroll
                for (int ni = 0; ni < 4; ni++)
                    mma_f16(acc[mi][ni], a[mi], b2[ni >> 1][ni & 1], b2[ni >> 1][(ni & 1) + 2]);
        }

        if (kt + 3 < NKT) {
            uint32_t sb = smem_u32 + ((kt + 3) & 3) * STGB;
            int k0 = (kt + 3) * BKH;
            #pragma unroll
            for (int i = 0; i < 2; i++) cp_async16(sb + aOff[i], aSrc[i] + k0);
            #pragma unroll
            for (int i = 0; i < 2; i++) cp_async16(sb + bOff[i], bSrc[i] + k0);
            CP_COMMIT();
        }
    }

    // ---- epilogue ----
    #pragma unroll
    for (int ni = 0; ni < 4; ni++) {
        int col = bx * BN + wn + ni * 8 + 2 * (lane & 3);
        float bv0 = bias[col], bv1 = bias[col + 1];
        #pragma unroll
        for (int mi = 0; mi < 4; mi++) {
            const float* a = acc[mi][ni];
            int m0 = by * BM + wm + mi * 16 + (lane >> 2);
            int m1 = m0 + 8;
            float o00 = alpha * (a[0] + bv0), o01 = alpha * (a[1] + bv1);
            float o10 = alpha * (a[2] + bv0), o11 = alpha * (a[3] + bv1);
            if (remap_out == 2) {
                out[((size_t)((m0 >> 12) * (NH*NL) + col    )) * SEQ + (m0 & (SEQ-1))] = o00;
                out[((size_t)((m0 >> 12) * (NH*NL) + col + 1)) * SEQ + (m0 & (SEQ-1))] = o01;
                out[((size_t)((m1 >> 12) * (NH*NL) + col    )) * SEQ + (m1 & (SEQ-1))] = o10;
                out[((size_t)((m1 >> 12) * (NH*NL) + col + 1)) * SEQ + (m1 & (SEQ-1))] = o11;
            } else {
                size_t r0 = remap_out ? ((size_t)(m0 & (SEQ-1)) * BATCH + (m0 >> 12)) : (size_t)m0;
                size_t r1 = remap_out ? ((size_t)(m1 & (SEQ-1)) * BATCH + (m1 >> 12)) : (size_t)m1;
                *(float2*)(out + r0 * N + col) = make_float2(o00, o01);
                *(float2*)(out + r1 * N + col) = make_float2(o10, o11);
            }
        }
    }
}

// ---------------- layernorm over last dim (1024), in place ----------------
__global__ void __launch_bounds__(256)
ln_kernel(float* __restrict__ data, const float* __restrict__ gamma,
          const float* __restrict__ beta)
{
    __shared__ float sh[32];
    const size_t row = blockIdx.x;
    float* p = data + row * DIMN;
    const int t = threadIdx.x;
    float4 v = ((const float4*)p)[t];
    float s = v.x + v.y + v.z + v.w;
    float mean = blk_sum256(s, sh) * (1.f / DIMN);
    float4 dx = {v.x - mean, v.y - mean, v.z - mean, v.w - mean};
    float sq = dx.x*dx.x + dx.y*dx.y + dx.z*dx.z + dx.w*dx.w;
    float var = blk_sum256(sq, sh) * (1.f / DIMN);
    float rstd = rsqrtf(var + 1e-5f);
    float4 g4 = ((const float4*)gamma)[t];
    float4 b4 = ((const float4*)beta)[t];
    float4 o4;
    o4.x = dx.x * rstd * g4.x + b4.x;
    o4.y = dx.y * rstd * g4.y + b4.y;
    o4.z = dx.z * rstd * g4.z + b4.z;
    o4.w = dx.w * rstd * g4.w + b4.w;
    ((float4*)p)[t] = o4;
}

// ---------------- softmax over contiguous rows of Dt ----------------
__global__ void __launch_bounds__(256)
dsoftmax_kernel(float* __restrict__ Dt)
{
    __shared__ float sh[32];
    float* p = Dt + (size_t)blockIdx.x * SEQ;
    const int t = threadIdx.x;
    float4 v[4];
    float mx = -1e30f;
    #pragma unroll
    for (int i = 0; i < 4; i++) {
        v[i] = ((const float4*)p)[t + i * 256];
        mx = fmaxf(mx, fmaxf(fmaxf(v[i].x, v[i].y), fmaxf(v[i].z, v[i].w)));
    }
    mx = blk_max256(mx, sh);
    float sum = 0.f;
    #pragma unroll
    for (int i = 0; i < 4; i++) {
        v[i].x = expf(v[i].x - mx); v[i].y = expf(v[i].y - mx);
        v[i].z = expf(v[i].z - mx); v[i].w = expf(v[i].w - mx);
        sum += v[i].x + v[i].y + v[i].z + v[i].w;
    }
    sum = blk_sum256(sum, sh);
    float inv = 1.f / sum;
    #pragma unroll
    for (int i = 0; i < 4; i++) {
        v[i].x *= inv; v[i].y *= inv; v[i].z *= inv; v[i].w *= inv;
        ((float4*)p)[t + i * 256] = v[i];
    }
}

// ---------------- compression partials ----------------
__global__ void __launch_bounds__(256)
compress_kernel(const float* __restrict__ Dt, const float* __restrict__ K,
                const float* __restrict__ V,
                float* __restrict__ partK, float* __restrict__ partV)
{
    const int bh = blockIdx.x;
    const int chunk = blockIdx.y;
    const int b = bh >> 4, h = bh & 15;
    const int t = threadIdx.x;
    const int d = t & 63;
    const int lbase = (t >> 6) * 8;

    __shared__ float sh_hs[NL][36];
    __shared__ float sh_K[32][64];
    __shared__ float sh_V[32][64];

    float accK[8], accV[8];
    #pragma unroll
    for (int i = 0; i < 8; i++) { accK[i] = 0.f; accV[i] = 0.f; }

    const int lrow = t >> 3;
    const int s4   = (t & 7) * 4;
    const float* dtrow = Dt + ((size_t)(b * (NH*NL) + h * NL + lrow)) * SEQ;
    const int kvr = t >> 4;
    const int d4  = (t & 15) * 4;

    const int s0c = chunk * CHUNK;
    for (int stage = 0; stage < CHUNK / 32; stage++) {
        const int sbase = s0c + stage * 32;
        __syncthreads();
        float4 hv = *(const float4*)(dtrow + sbase + s4);
        *(float4*)&sh_hs[lrow][s4] = hv;
        #pragma unroll
        for (int i = 0; i < 2; i++) {
            int si = kvr + i * 16;
            size_t src = ((size_t)(b * SEQ + sbase + si)) * DIMN + h * DH + d4;
            *(float4*)&sh_K[si][d4] = *(const float4*)(K + src);
            *(float4*)&sh_V[si][d4] = *(const float4*)(V + src);
        }
        __syncthreads();
        #pragma unroll 4
        for (int si = 0; si < 32; si++) {
            float kv = sh_K[si][d], vv = sh_V[si][d];
            #pragma unroll
            for (int li = 0; li < 8; li++) {
                float hsv = sh_hs[lbase + li][si];
                accK[li] = fmaf(hsv, kv, accK[li]);
                accV[li] = fmaf(hsv, vv, accV[li]);
            }
        }
    }
    #pragma unroll
    for (int li = 0; li < 8; li++) {
        size_t idx = (((size_t)bh * NCH + chunk) * NL + lbase + li) * DH + d;
        partK[idx] = accK[li];
        partV[idx] = accV[li];
    }
}

// ---------------- reduce partials -> Kc/Vc ----------------
__global__ void __launch_bounds__(256)
reduce_kc(const float* __restrict__ partK, const float* __restrict__ partV,
          float* __restrict__ Kc, float* __restrict__ Vc)
{
    const int e = blockIdx.x * 256 + threadIdx.x;
    const int d = e & 63;
    const int h = (e >> 6) & 15;
    const int l = (e >> 10) & 31;
    const int b = e >> 15;
    const int bh = b * NH + h;
    float sK = 0.f, sV = 0.f;
    #pragma unroll
    for (int c = 0; c < NCH; c++) {
        size_t idx = (((size_t)bh * NCH + c) * NL + l) * DH + d;
        sK += partK[idx];
        sV += partV[idx];
    }
    size_t o = ((size_t)(b * NL + l)) * DIMN + h * DH + d;
    Kc[o] = sK;
    Vc[o] = sV;
}

// ---------------- fused attention ----------------
#define GPB 2
#define NQ  (GPB*WW)
#define NWK ((GPB-1)*WW + BAND)

__global__ void __launch_bounds__(256)
attn_kernel(const float* __restrict__ Q, const float* __restrict__ K,
            const float* __restrict__ V, const float* __restrict__ Kc,
            const float* __restrict__ Vc, __half* __restrict__ C)
{
    const int gblk = blockIdx.x;
    const int h = blockIdx.y;
    const int b = blockIdx.z;
    const int s0  = gblk * NQ;
    const int wk0 = s0 - EE;

    __shared__ float sKc[NL][68];
    __shared__ float sVc[NL][68];
    __shared__ float sKw[NWK][68];
    __shared__ float sVw[NWK][68];
    __shared__ float sQ [NQ][68];
    __shared__ float sp [NQ][48];

    const int t = threadIdx.x;

    for (int i = t; i < NL * DH; i += 256) {
        int l = i >> 6, d = i & 63;
        size_t src = ((size_t)(b * NL + l)) * DIMN + h * DH + d;
        sKc[l][d] = Kc[src];
        sVc[l][d] = Vc[src];
    }
    for (int i = t; i < NQ * DH; i += 256) {
        int q = i >> 6, d = i & 63;
        sQ[q][d] = Q[((size_t)(b * SEQ + s0 + q)) * DIMN + h * DH + d];
    }
    for (int i = t; i < NWK * DH; i += 256) {
        int r = i >> 6, d = i & 63;
        int sk = wk0 + r;
        float kv = 0.f, vv = 0.f;
        if (sk >= 0 && sk < SEQ) {
            size_t src = ((size_t)(b * SEQ + sk)) * DIMN + h * DH + d;
            kv = K[src]; vv = V[src];
        }
        sKw[r][d] = kv;
        sVw[r][d] = vv;
    }
    __syncthreads();

    const int warp = t >> 5, lane = t & 31;
    #pragma unroll
    for (int qq = 0; qq < 2; qq++) {
        const int q = warp * 2 + qq;
        const int grp = q >> 3;
        const int woff = grp * WW;
        const float* qrow  = sQ[q];
        const float* krow0 = sKc[lane];
        const float* krow1 = sKw[woff + (lane & 15)];
        float sc0 = 0.f, sc1 = 0.f;
        #pragma unroll
        for (int dd = 0; dd < DH; dd += 4) {
            float4 qa = *(const float4*)(qrow + dd);
            float4 ka = *(const float4*)(krow0 + dd);
            float4 kb = *(const float4*)(krow1 + dd);
            sc0 += qa.x*ka.x + qa.y*ka.y + qa.z*ka.z + qa.w*ka.w;
            sc1 += qa.x*kb.x + qa.y*kb.y + qa.z*kb.z + qa.w*kb.w;
        }
        bool wvalid = (lane < 16);
        if (wvalid) {
            int sk = wk0 + woff + lane;
            if (sk < 0 || sk >= SEQ) wvalid = false;
        }
        float swin = wvalid ? sc1 : -1e30f;
        float m = fmaxf(sc0, swin);
        #pragma unroll
        for (int o = 16; o; o >>= 1) m = fmaxf(m, __shfl_xor_sync(0xffffffffu, m, o));
        float e0 = expf(sc0 - m);
        float e1 = wvalid ? expf(swin - m) : 0.f;
        float ssum = e0 + e1;
        #pragma unroll
        for (int o = 16; o; o >>= 1) ssum += __shfl_xor_sync(0xffffffffu, ssum, o);
        float inv = 1.f / ssum;
        sp[q][lane] = e0 * inv;
        if (lane < 16) sp[q][32 + lane] = e1 * inv;
    }
    __syncthreads();

    for (int i = t; i < NQ * DH; i += 256) {
        int q = i >> 6, d = i & 63;
        int woff = (q >> 3) * WW;
        float acc = 0.f;
        #pragma unroll
        for (int l = 0; l < NL; l++) acc = fmaf(sp[q][l], sVc[l][d], acc);
        #pragma unroll
        for (int j = 0; j < BAND; j++) acc = fmaf(sp[q][32 + j], sVw[woff + j][d], acc);
        C[((size_t)(b * SEQ + s0 + q)) * DIMN + h * DH + d] = __float2half_rn(acc);
    }
}

// ---------------- launch ----------------
extern "C" void kernel_launch(void* const* d_in, const int* in_sizes, int n_in,
                              void* d_out, int out_size)
{
    const float* query = (const float*)d_in[0];
    const float* Wq  = (const float*)d_in[1];
    const float* bq  = (const float*)d_in[2];
    const float* Wk  = (const float*)d_in[3];
    const float* bk  = (const float*)d_in[4];
    const float* Wv  = (const float*)d_in[5];
    const float* bv  = (const float*)d_in[6];
    const float* Wo  = (const float*)d_in[7];
    const float* bo  = (const float*)d_in[8];
    const float* g_l = (const float*)d_in[9];
    const float* b_l = (const float*)d_in[10];
    const float* g_s = (const float*)d_in[11];
    const float* b_s = (const float*)d_in[12];
    const float* Wd  = (const float*)d_in[13];
    const float* bd  = (const float*)d_in[14];
    float* out = (float*)d_out;

    float *Qb, *Kb, *Vb, *Db, *Kcb, *Vcb, *pK, *pV;
    __half *Ah, *Wh, *Ch;
    cudaGetSymbolAddress((void**)&Qb,  g_Q);
    cudaGetSymbolAddress((void**)&Kb,  g_K);
    cudaGetSymbolAddress((void**)&Vb,  g_V);
    cudaGetSymbolAddress((void**)&Db,  g_Ds);
    cudaGetSymbolAddress((void**)&Kcb, g_Kc);
    cudaGetSymbolAddress((void**)&Vcb, g_Vc);
    cudaGetSymbolAddress((void**)&pK,  g_pK);
    cudaGetSymbolAddress((void**)&pV,  g_pV);
    cudaGetSymbolAddress((void**)&Ah,  g_Ah);
    cudaGetSymbolAddress((void**)&Wh,  g_Wh);
    cudaGetSymbolAddress((void**)&Ch,  g_Ch);

    static int smem_set = 0;
    if (!smem_set) {
        cudaFuncSetAttribute(gemm_fp16, cudaFuncAttributeMaxDynamicSharedMemorySize, GEMM_SMEM);
        smem_set = 1;
    }

    const size_t WSZ = (size_t)DIMN * DIMN;
    __half* tWq = Wh;            // [1024][1024] n-major (K contiguous)
    __half* tWk = Wh + WSZ;
    __half* tWv = Wh + 2 * WSZ;
    __half* tWo = Wh + 3 * WSZ;
    __half* tWd = Wh + 4 * WSZ;  // [512][1024]

    // fp16 conversion: query (row-major) + transposed weights
    convert_half_kernel<<<(MROWS*DIMN/4 + 255)/256, 256>>>(query, Ah, MROWS*DIMN/4);
    transpose_half_kernel<<<dim3(32, 32), 256>>>(Wq, tWq, DIMN, DIMN);
    transpose_half_kernel<<<dim3(32, 32), 256>>>(Wk, tWk, DIMN, DIMN);
    transpose_half_kernel<<<dim3(32, 32), 256>>>(Wv, tWv, DIMN, DIMN);
    transpose_half_kernel<<<dim3(32, 32), 256>>>(Wo, tWo, DIMN, DIMN);
    transpose_half_kernel<<<dim3(16, 32), 256>>>(Wd, tWd, DIMN, NH*NL);

    // Projections (fp16 tensor cores, fp32 accumulate)
    gemm_fp16<<<dim3(8, 128), 256, GEMM_SMEM>>>(Ah, tWq, bq, Qb, 1024, 0.125f, 1, 0);
    gemm_fp16<<<dim3(8, 128), 256, GEMM_SMEM>>>(Ah, tWk, bk, Kb, 1024, 1.0f,   1, 0);
    gemm_fp16<<<dim3(8, 128), 256, GEMM_SMEM>>>(Ah, tWv, bv, Vb, 1024, 1.0f,   1, 0);
    gemm_fp16<<<dim3(4, 128), 256, GEMM_SMEM>>>(Ah, tWd, bd, Db,  512, 1.0f,   1, 2);

    // LayerNorm on K, V
    ln_kernel<<<MROWS, 256>>>(Kb, g_l, b_l);
    ln_kernel<<<MROWS, 256>>>(Vb, g_l, b_l);

    // head_scores softmax over sequence axis
    dsoftmax_kernel<<<BATCH * NH * NL, 256>>>(Db);

    // Compression
    compress_kernel<<<dim3(BATCH * NH, NCH), 256>>>(Db, Kb, Vb, pK, pV);
    reduce_kc<<<(BATCH * NL * DIMN) / 256, 256>>>(pK, pV, Kcb, Vcb);

    // LayerNorm on compressed K/V
    ln_kernel<<<BATCH * NL, 256>>>(Kcb, g_s, b_s);
    ln_kernel<<<BATCH * NL, 256>>>(Vcb, g_s, b_s);

    // Fused long-short attention (writes fp16 C for the Wo GEMM)
    attn_kernel<<<dim3(SEQ / NQ, NH, BATCH), 256>>>(Qb, Kb, Vb, Kcb, Vcb, Ch);

    // Output projection with transposed write to (s, b, DIM)
    gemm_fp16<<<dim3(8, 128), 256, GEMM_SMEM>>>(Ch, tWo, bo, out, 1024, 1.0f, 0, 1);
}

// round 13
// speedup vs baseline: 1.4410x; 1.0178x over previous
#include <cuda_runtime.h>
#include <cuda_fp16.h>
#include <math.h>
#include <stdint.h>

#define SEQ   4096
#define BATCH 4
#define DIMN  1024
#define NH    16
#define DH    64
#define NL    32
#define WW    8
#define EE    4
#define BAND  16
#define MROWS (BATCH*SEQ)
#define NCH   8
#define CHUNK (SEQ/NCH)

// ---------------- scratch ----------------
__device__ float  g_Q [(size_t)BATCH*SEQ*DIMN];
__device__ float  g_K [(size_t)BATCH*SEQ*DIMN];
__device__ float  g_V [(size_t)BATCH*SEQ*DIMN];
__device__ float  g_Ds[(size_t)BATCH*SEQ*NH*NL];   // transposed: (b, c=512, s=4096)
__device__ float  g_Kc[(size_t)BATCH*NL*DIMN];
__device__ float  g_Vc[(size_t)BATCH*NL*DIMN];
__device__ float  g_pK[(size_t)BATCH*NH*NCH*NL*DH];
__device__ float  g_pV[(size_t)BATCH*NH*NCH*NL*DH];
__device__ __half g_Ah[(size_t)MROWS*DIMN];                // fp16 query
__device__ __half g_Wh[(size_t)4*DIMN*DIMN + DIMN*NH*NL];  // fp16 transposed weights [n][k]
__device__ __half g_Ch[(size_t)BATCH*SEQ*DIMN];            // fp16 attention output

// ---------------- PTX helpers ----------------
__device__ __forceinline__ void mma_f16(float* c, const uint32_t* a, uint32_t b0, uint32_t b1) {
    asm volatile(
        "mma.sync.aligned.m16n8k16.row.col.f32.f16.f16.f32 "
        "{%0,%1,%2,%3}, {%4,%5,%6,%7}, {%8,%9}, {%0,%1,%2,%3};"
        : "+f"(c[0]), "+f"(c[1]), "+f"(c[2]), "+f"(c[3])
        : "r"(a[0]), "r"(a[1]), "r"(a[2]), "r"(a[3]), "r"(b0), "r"(b1));
}

__device__ __forceinline__ void ldsm_x4(uint32_t* r, uint32_t addr) {
    asm volatile("ldmatrix.sync.aligned.m8n8.x4.shared.b16 {%0,%1,%2,%3}, [%4];"
        : "=r"(r[0]), "=r"(r[1]), "=r"(r[2]), "=r"(r[3]) : "r"(addr));
}

__device__ __forceinline__ void cp_async16(uint32_t dst, const void* src) {
    asm volatile("cp.async.cg.shared.global [%0], [%1], 16;" :: "r"(dst), "l"(src));
}
#define CP_COMMIT() asm volatile("cp.async.commit_group;")
#define CP_WAIT1()  asm volatile("cp.async.wait_group 1;")
#define CP_WAIT0()  asm volatile("cp.async.wait_group 0;")

// ---------------- block reductions ----------------
__device__ __forceinline__ float blk_sum256(float v, float* sh) {
    int t = threadIdx.x;
    #pragma unroll
    for (int o = 16; o; o >>= 1) v += __shfl_xor_sync(0xffffffffu, v, o);
    if ((t & 31) == 0) sh[t >> 5] = v;
    __syncthreads();
    if (t < 32) {
        float x = (t < 8) ? sh[t] : 0.f;
        #pragma unroll
        for (int o = 4; o; o >>= 1) x += __shfl_xor_sync(0xffffffffu, x, o);
        if (t == 0) sh[0] = x;
    }
    __syncthreads();
    float r = sh[0];
    __syncthreads();
    return r;
}

__device__ __forceinline__ float blk_max256(float v, float* sh) {
    int t = threadIdx.x;
    #pragma unroll
    for (int o = 16; o; o >>= 1) v = fmaxf(v, __shfl_xor_sync(0xffffffffu, v, o));
    if ((t & 31) == 0) sh[t >> 5] = v;
    __syncthreads();
    if (t < 32) {
        float x = (t < 8) ? sh[t] : -1e30f;
        #pragma unroll
        for (int o = 4; o; o >>= 1) x = fmaxf(x, __shfl_xor_sync(0xffffffffu, x, o));
        if (t == 0) sh[0] = x;
    }
    __syncthreads();
    float r = sh[0];
    __syncthreads();
    return r;
}

// ---------------- fp16 conversion passes ----------------
__global__ void __launch_bounds__(256)
convert_half_kernel(const float* __restrict__ src, __half* __restrict__ dst, int n4)
{
    int i = blockIdx.x * 256 + threadIdx.x;
    if (i < n4) {
        float4 v = ((const float4*)src)[i];
        __half2 h0 = __floats2half2_rn(v.x, v.y);
        __half2 h1 = __floats2half2_rn(v.z, v.w);
        ((__half2*)dst)[2*i]   = h0;
        ((__half2*)dst)[2*i+1] = h1;
    }
}

// src [R][C] f32 -> dst [C][R] f16
__global__ void __launch_bounds__(256)
transpose_half_kernel(const float* __restrict__ src, __half* __restrict__ dst,
                      int R, int C)
{
    __shared__ float tl[32][33];
    const int tx = threadIdx.x & 31, ty = threadIdx.x >> 5;   // 32x8
    const int c0 = blockIdx.x * 32, r0 = blockIdx.y * 32;
    #pragma unroll
    for (int j = 0; j < 4; j++)
        tl[ty + j * 8][tx] = src[(size_t)(r0 + ty + j * 8) * C + c0 + tx];
    __syncthreads();
    #pragma unroll
    for (int j = 0; j < 4; j++)
        dst[(size_t)(c0 + ty + j * 8) * R + r0 + tx] =
            __float2half_rn(tl[tx][ty + j * 8]);
}

// ---------------- fp16 tensor-core GEMM ----------------
// out = alpha*(A@W + bias). A fp16 (16384 x 1024); Wt fp16 [N][1024] K-major.
// remap_in: A row m=(b*S+s) at A[(s*B+b)]; remap_out: 0 direct, 1 transpose rows, 2 D-transpose.
#define BM 128
#define BN 128
#define BKH 64                    // halfs of K per stage (128B rows, SW128)
#define NKT (DIMN/BKH)            // 16
#define ABYTES (BM*BKH*2)         // 16384
#define STGB  (2*ABYTES)          // 32768 (A + B)
#define GEMM_SMEM (3*STGB)        // 98304, 3-stage ring

__global__ void __launch_bounds__(256, 2)
gemm_fp16(const __half* __restrict__ A, const __half* __restrict__ Wt,
          const float* __restrict__ bias, float* __restrict__ out,
          int N, float alpha, int remap_in, int remap_out)
{
    extern __shared__ __half smh[];
    const uint32_t smem_u32 = (uint32_t)__cvta_generic_to_shared(smh);
    const int t = threadIdx.x;
    const int bx = blockIdx.x, by = blockIdx.y;
    const int lane = t & 31, warp = t >> 5;
    const int wm = (warp & 1) * 64;    // 2 warps in M
    const int wn = (warp >> 1) * 32;   // 4 warps in N

    // ---- cp.async mapping: stages are 128 rows x 64 halfs (128B rows, 8x16B chunks)
    // SW128 swizzle: chunk_swz = c ^ (row & 7)
    const __half* aSrc[4]; uint32_t aOff[4];
    const __half* bSrc[4]; uint32_t bOff[4];
    #pragma unroll
    for (int i = 0; i < 4; i++) {
        int idx = t + i * 256;          // 0..1023
        int row = idx >> 3, c = idx & 7;
        int m = by * BM + row;
        size_t arow = remap_in ? ((size_t)(m & (SEQ-1)) * BATCH + (m >> 12)) : (size_t)m;
        aSrc[i] = A + arow * DIMN + c * 8;
        aOff[i] = (uint32_t)(row * 128 + ((c ^ (row & 7)) * 16));
        int n = bx * BN + row;
        bSrc[i] = Wt + (size_t)n * DIMN + c * 8;
        bOff[i] = (uint32_t)(ABYTES + row * 128 + ((c ^ (row & 7)) * 16));
    }

    float acc[4][4][4];
    #pragma unroll
    for (int mi = 0; mi < 4; mi++)
        #pragma unroll
        for (int ni = 0; ni < 4; ni++)
            #pragma unroll
            for (int r = 0; r < 4; r++) acc[mi][ni][r] = 0.f;

    // ---- prologue: stages 0..1 ----
    #pragma unroll
    for (int s = 0; s < 2; s++) {
        uint32_t sb = smem_u32 + s * STGB;
        int k0 = s * BKH;
        #pragma unroll
        for (int i = 0; i < 4; i++) cp_async16(sb + aOff[i], aSrc[i] + k0);
        #pragma unroll
        for (int i = 0; i < 4; i++) cp_async16(sb + bOff[i], bSrc[i] + k0);
        CP_COMMIT();
    }

    const int r15 = lane & 15;
    const int chi = lane >> 4;     // 0/1: which 16B chunk of the k16 slice
    const int swx = r15 & 7;

    int stg = 0;                   // consume stage = kt % 3
    #pragma unroll 1
    for (int kt = 0; kt < NKT; kt++) {
        if (kt < NKT - 1) { CP_WAIT1(); } else { CP_WAIT0(); }
        __syncthreads();

        uint32_t sA = smem_u32 + stg * STGB;
        uint32_t sB = sA + ABYTES;

        #pragma unroll
        for (int kb = 0; kb < 4; kb++) {       // 4 x k16 within the 64-half stage
            uint32_t a[4][4], b2[2][4];
            uint32_t sw = (uint32_t)((((kb * 2 + chi) ^ swx) & 7) * 16);
            #pragma unroll
            for (int mi = 0; mi < 4; mi++)
                ldsm_x4(a[mi], sA + (wm + mi * 16 + r15) * 128 + sw);
            #pragma unroll
            for (int nh = 0; nh < 2; nh++)
                ldsm_x4(b2[nh], sB + (wn + nh * 16 + r15) * 128 + sw);
            #pragma unroll
            for (int mi = 0; mi < 4; mi++)
                #pragma unroll
                for (int ni = 0; ni < 4; ni++)
                    mma_f16(acc[mi][ni], a[mi], b2[ni >> 1][ni & 1], b2[ni >> 1][(ni & 1) + 2]);
        }

        if (kt + 2 < NKT) {
            // prefetch for k-tile kt+2 -> stage (kt+2) % 3 == (stg + 2) % 3
            int pst = stg + 2; if (pst >= 3) pst -= 3;
            uint32_t sb = smem_u32 + pst * STGB;
            int k0 = (kt + 2) * BKH;
            #pragma unroll
            for (int i = 0; i < 4; i++) cp_async16(sb + aOff[i], aSrc[i] + k0);
            #pragma unroll
            for (int i = 0; i < 4; i++) cp_async16(sb + bOff[i], bSrc[i] + k0);
            CP_COMMIT();
        }
        stg = (stg == 2) ? 0 : stg + 1;
    }

    // ---- epilogue ----
    #pragma unroll
    for (int ni = 0; ni < 4; ni++) {
        int col = bx * BN + wn + ni * 8 + 2 * (lane & 3);
        float bv0 = bias[col], bv1 = bias[col + 1];
        #pragma unroll
        for (int mi = 0; mi < 4; mi++) {
            const float* a = acc[mi][ni];
            int m0 = by * BM + wm + mi * 16 + (lane >> 2);
            int m1 = m0 + 8;
            float o00 = alpha * (a[0] + bv0), o01 = alpha * (a[1] + bv1);
            float o10 = alpha * (a[2] + bv0), o11 = alpha * (a[3] + bv1);
            if (remap_out == 2) {
                out[((size_t)((m0 >> 12) * (NH*NL) + col    )) * SEQ + (m0 & (SEQ-1))] = o00;
                out[((size_t)((m0 >> 12) * (NH*NL) + col + 1)) * SEQ + (m0 & (SEQ-1))] = o01;
                out[((size_t)((m1 >> 12) * (NH*NL) + col    )) * SEQ + (m1 & (SEQ-1))] = o10;
                out[((size_t)((m1 >> 12) * (NH*NL) + col + 1)) * SEQ + (m1 & (SEQ-1))] = o11;
            } else {
                size_t r0 = remap_out ? ((size_t)(m0 & (SEQ-1)) * BATCH + (m0 >> 12)) : (size_t)m0;
                size_t r1 = remap_out ? ((size_t)(m1 & (SEQ-1)) * BATCH + (m1 >> 12)) : (size_t)m1;
                *(float2*)(out + r0 * N + col) = make_float2(o00, o01);
                *(float2*)(out + r1 * N + col) = make_float2(o10, o11);
            }
        }
    }
}

// ---------------- layernorm over last dim (1024), in place ----------------
__global__ void __launch_bounds__(256)
ln_kernel(float* __restrict__ data, const float* __restrict__ gamma,
          const float* __restrict__ beta)
{
    __shared__ float sh[32];
    const size_t row = blockIdx.x;
    float* p = data + row * DIMN;
    const int t = threadIdx.x;
    float4 v = ((const float4*)p)[t];
    float s = v.x + v.y + v.z + v.w;
    float mean = blk_sum256(s, sh) * (1.f / DIMN);
    float4 dx = {v.x - mean, v.y - mean, v.z - mean, v.w - mean};
    float sq = dx.x*dx.x + dx.y*dx.y + dx.z*dx.z + dx.w*dx.w;
    float var = blk_sum256(sq, sh) * (1.f / DIMN);
    float rstd = rsqrtf(var + 1e-5f);
    float4 g4 = ((const float4*)gamma)[t];
    float4 b4 = ((const float4*)beta)[t];
    float4 o4;
    o4.x = dx.x * rstd * g4.x + b4.x;
    o4.y = dx.y * rstd * g4.y + b4.y;
    o4.z = dx.z * rstd * g4.z + b4.z;
    o4.w = dx.w * rstd * g4.w + b4.w;
    ((float4*)p)[t] = o4;
}

// ---------------- softmax over contiguous rows of Dt ----------------
__global__ void __launch_bounds__(256)
dsoftmax_kernel(float* __restrict__ Dt)
{
    __shared__ float sh[32];
    float* p = Dt + (size_t)blockIdx.x * SEQ;
    const int t = threadIdx.x;
    float4 v[4];
    float mx = -1e30f;
    #pragma unroll
    for (int i = 0; i < 4; i++) {
        v[i] = ((const float4*)p)[t + i * 256];
        mx = fmaxf(mx, fmaxf(fmaxf(v[i].x, v[i].y), fmaxf(v[i].z, v[i].w)));
    }
    mx = blk_max256(mx, sh);
    float sum = 0.f;
    #pragma unroll
    for (int i = 0; i < 4; i++) {
        v[i].x = expf(v[i].x - mx); v[i].y = expf(v[i].y - mx);
        v[i].z = expf(v[i].z - mx); v[i].w = expf(v[i].w - mx);
        sum += v[i].x + v[i].y + v[i].z + v[i].w;
    }
    sum = blk_sum256(sum, sh);
    float inv = 1.f / sum;
    #pragma unroll
    for (int i = 0; i < 4; i++) {
        v[i].x *= inv; v[i].y *= inv; v[i].z *= inv; v[i].w *= inv;
        ((float4*)p)[t + i * 256] = v[i];
    }
}

// ---------------- compression partials ----------------
__global__ void __launch_bounds__(256)
compress_kernel(const float* __restrict__ Dt, const float* __restrict__ K,
                const float* __restrict__ V,
                float* __restrict__ partK, float* __restrict__ partV)
{
    const int bh = blockIdx.x;
    const int chunk = blockIdx.y;
    const int b = bh >> 4, h = bh & 15;
    const int t = threadIdx.x;
    const int d = t & 63;
    const int lbase = (t >> 6) * 8;

    __shared__ float sh_hs[NL][36];
    __shared__ float sh_K[32][64];
    __shared__ float sh_V[32][64];

    float accK[8], accV[8];
    #pragma unroll
    for (int i = 0; i < 8; i++) { accK[i] = 0.f; accV[i] = 0.f; }

    const int lrow = t >> 3;
    const int s4   = (t & 7) * 4;
    const float* dtrow = Dt + ((size_t)(b * (NH*NL) + h * NL + lrow)) * SEQ;
    const int kvr = t >> 4;
    const int d4  = (t & 15) * 4;

    const int s0c = chunk * CHUNK;
    for (int stage = 0; stage < CHUNK / 32; stage++) {
        const int sbase = s0c + stage * 32;
        __syncthreads();
        float4 hv = *(const float4*)(dtrow + sbase + s4);
        *(float4*)&sh_hs[lrow][s4] = hv;
        #pragma unroll
        for (int i = 0; i < 2; i++) {
            int si = kvr + i * 16;
            size_t src = ((size_t)(b * SEQ + sbase + si)) * DIMN + h * DH + d4;
            *(float4*)&sh_K[si][d4] = *(const float4*)(K + src);
            *(float4*)&sh_V[si][d4] = *(const float4*)(V + src);
        }
        __syncthreads();
        #pragma unroll 4
        for (int si = 0; si < 32; si++) {
            float kv = sh_K[si][d], vv = sh_V[si][d];
            #pragma unroll
            for (int li = 0; li < 8; li++) {
                float hsv = sh_hs[lbase + li][si];
                accK[li] = fmaf(hsv, kv, accK[li]);
                accV[li] = fmaf(hsv, vv, accV[li]);
            }
        }
    }
    #pragma unroll
    for (int li = 0; li < 8; li++) {
        size_t idx = (((size_t)bh * NCH + chunk) * NL + lbase + li) * DH + d;
        partK[idx] = accK[li];
        partV[idx] = accV[li];
    }
}

// ---------------- reduce partials -> Kc/Vc ----------------
__global__ void __launch_bounds__(256)
reduce_kc(const float* __restrict__ partK, const float* __restrict__ partV,
          float* __restrict__ Kc, float* __restrict__ Vc)
{
    const int e = blockIdx.x * 256 + threadIdx.x;
    const int d = e & 63;
    const int h = (e >> 6) & 15;
    const int l = (e >> 10) & 31;
    const int b = e >> 15;
    const int bh = b * NH + h;
    float sK = 0.f, sV = 0.f;
    #pragma unroll
    for (int c = 0; c < NCH; c++) {
        size_t idx = (((size_t)bh * NCH + c) * NL + l) * DH + d;
        sK += partK[idx];
        sV += partV[idx];
    }
    size_t o = ((size_t)(b * NL + l)) * DIMN + h * DH + d;
    Kc[o] = sK;
    Vc[o] = sV;
}

// ---------------- fused attention ----------------
#define GPB 2
#define NQ  (GPB*WW)
#define NWK ((GPB-1)*WW + BAND)

__global__ void __launch_bounds__(256)
attn_kernel(const float* __restrict__ Q, const float* __restrict__ K,
            const float* __restrict__ V, const float* __restrict__ Kc,
            const float* __restrict__ Vc, __half* __restrict__ C)
{
    const int gblk = blockIdx.x;
    const int h = blockIdx.y;
    const int b = blockIdx.z;
    const int s0  = gblk * NQ;
    const int wk0 = s0 - EE;

    __shared__ float sKc[NL][68];
    __shared__ float sVc[NL][68];
    __shared__ float sKw[NWK][68];
    __shared__ float sVw[NWK][68];
    __shared__ float sQ [NQ][68];
    __shared__ float sp [NQ][48];

    const int t = threadIdx.x;

    for (int i = t; i < NL * DH; i += 256) {
        int l = i >> 6, d = i & 63;
        size_t src = ((size_t)(b * NL + l)) * DIMN + h * DH + d;
        sKc[l][d] = Kc[src];
        sVc[l][d] = Vc[src];
    }
    for (int i = t; i < NQ * DH; i += 256) {
        int q = i >> 6, d = i & 63;
        sQ[q][d] = Q[((size_t)(b * SEQ + s0 + q)) * DIMN + h * DH + d];
    }
    for (int i = t; i < NWK * DH; i += 256) {
        int r = i >> 6, d = i & 63;
        int sk = wk0 + r;
        float kv = 0.f, vv = 0.f;
        if (sk >= 0 && sk < SEQ) {
            size_t src = ((size_t)(b * SEQ + sk)) * DIMN + h * DH + d;
            kv = K[src]; vv = V[src];
        }
        sKw[r][d] = kv;
        sVw[r][d] = vv;
    }
    __syncthreads();

    const int warp = t >> 5, lane = t & 31;
    #pragma unroll
    for (int qq = 0; qq < 2; qq++) {
        const int q = warp * 2 + qq;
        const int grp = q >> 3;
        const int woff = grp * WW;
        const float* qrow  = sQ[q];
        const float* krow0 = sKc[lane];
        const float* krow1 = sKw[woff + (lane & 15)];
        float sc0 = 0.f, sc1 = 0.f;
        #pragma unroll
        for (int dd = 0; dd < DH; dd += 4) {
            float4 qa = *(const float4*)(qrow + dd);
            float4 ka = *(const float4*)(krow0 + dd);
            float4 kb = *(const float4*)(krow1 + dd);
            sc0 += qa.x*ka.x + qa.y*ka.y + qa.z*ka.z + qa.w*ka.w;
            sc1 += qa.x*kb.x + qa.y*kb.y + qa.z*kb.z + qa.w*kb.w;
        }
        bool wvalid = (lane < 16);
        if (wvalid) {
            int sk = wk0 + woff + lane;
            if (sk < 0 || sk >= SEQ) wvalid = false;
        }
        float swin = wvalid ? sc1 : -1e30f;
        float m = fmaxf(sc0, swin);
        #pragma unroll
        for (int o = 16; o; o >>= 1) m = fmaxf(m, __shfl_xor_sync(0xffffffffu, m, o));
        float e0 = expf(sc0 - m);
        float e1 = wvalid ? expf(swin - m) : 0.f;
        float ssum = e0 + e1;
        #pragma unroll
        for (int o = 16; o; o >>= 1) ssum += __shfl_xor_sync(0xffffffffu, ssum, o);
        float inv = 1.f / ssum;
        sp[q][lane] = e0 * inv;
        if (lane < 16) sp[q][32 + lane] = e1 * inv;
    }
    __syncthreads();

    for (int i = t; i < NQ * DH; i += 256) {
        int q = i >> 6, d = i & 63;
        int woff = (q >> 3) * WW;
        float acc = 0.f;
        #pragma unroll
        for (int l = 0; l < NL; l++) acc = fmaf(sp[q][l], sVc[l][d], acc);
        #pragma unroll
        for (int j = 0; j < BAND; j++) acc = fmaf(sp[q][32 + j], sVw[woff + j][d], acc);
        C[((size_t)(b * SEQ + s0 + q)) * DIMN + h * DH + d] = __float2half_rn(acc);
    }
}

// ---------------- launch ----------------
extern "C" void kernel_launch(void* const* d_in, const int* in_sizes, int n_in,
                              void* d_out, int out_size)
{
    const float* query = (const float*)d_in[0];
    const float* Wq  = (const float*)d_in[1];
    const float* bq  = (const float*)d_in[2];
    const float* Wk  = (const float*)d_in[3];
    const float* bk  = (const float*)d_in[4];
    const float* Wv  = (const float*)d_in[5];
    const float* bv  = (const float*)d_in[6];
    const float* Wo  = (const float*)d_in[7];
    const float* bo  = (const float*)d_in[8];
    const float* g_l = (const float*)d_in[9];
    const float* b_l = (const float*)d_in[10];
    const float* g_s = (const float*)d_in[11];
    const float* b_s = (const float*)d_in[12];
    const float* Wd  = (const float*)d_in[13];
    const float* bd  = (const float*)d_in[14];
    float* out = (float*)d_out;

    float *Qb, *Kb, *Vb, *Db, *Kcb, *Vcb, *pK, *pV;
    __half *Ah, *Wh, *Ch;
    cudaGetSymbolAddress((void**)&Qb,  g_Q);
    cudaGetSymbolAddress((void**)&Kb,  g_K);
    cudaGetSymbolAddress((void**)&Vb,  g_V);
    cudaGetSymbolAddress((void**)&Db,  g_Ds);
    cudaGetSymbolAddress((void**)&Kcb, g_Kc);
    cudaGetSymbolAddress((void**)&Vcb, g_Vc);
    cudaGetSymbolAddress((void**)&pK,  g_pK);
    cudaGetSymbolAddress((void**)&pV,  g_pV);
    cudaGetSymbolAddress((void**)&Ah,  g_Ah);
    cudaGetSymbolAddress((void**)&Wh,  g_Wh);
    cudaGetSymbolAddress((void**)&Ch,  g_Ch);

    static int smem_set = 0;
    if (!smem_set) {
        cudaFuncSetAttribute(gemm_fp16, cudaFuncAttributeMaxDynamicSharedMemorySize, GEMM_SMEM);
        smem_set = 1;
    }

    const size_t WSZ = (size_t)DIMN * DIMN;
    __half* tWq = Wh;            // [1024][1024] n-major (K contiguous)
    __half* tWk = Wh + WSZ;
    __half* tWv = Wh + 2 * WSZ;
    __half* tWo = Wh + 3 * WSZ;
    __half* tWd = Wh + 4 * WSZ;  // [512][1024]

    // fp16 conversion: query (row-major) + transposed weights
    convert_half_kernel<<<(MROWS*DIMN/4 + 255)/256, 256>>>(query, Ah, MROWS*DIMN/4);
    transpose_half_kernel<<<dim3(32, 32), 256>>>(Wq, tWq, DIMN, DIMN);
    transpose_half_kernel<<<dim3(32, 32), 256>>>(Wk, tWk, DIMN, DIMN);
    transpose_half_kernel<<<dim3(32, 32), 256>>>(Wv, tWv, DIMN, DIMN);
    transpose_half_kernel<<<dim3(32, 32), 256>>>(Wo, tWo, DIMN, DIMN);
    transpose_half_kernel<<<dim3(16, 32), 256>>>(Wd, tWd, DIMN, NH*NL);

    // Projections (fp16 tensor cores, fp32 accumulate)
    gemm_fp16<<<dim3(8, 128), 256, GEMM_SMEM>>>(Ah, tWq, bq, Qb, 1024, 0.125f, 1, 0);
    gemm_fp16<<<dim3(8, 128), 256, GEMM_SMEM>>>(Ah, tWk, bk, Kb, 1024, 1.0f,   1, 0);
    gemm_fp16<<<dim3(8, 128), 256, GEMM_SMEM>>>(Ah, tWv, bv, Vb, 1024, 1.0f,   1, 0);
    gemm_fp16<<<dim3(4, 128), 256, GEMM_SMEM>>>(Ah, tWd, bd, Db,  512, 1.0f,   1, 2);

    // LayerNorm on K, V
    ln_kernel<<<MROWS, 256>>>(Kb, g_l, b_l);
    ln_kernel<<<MROWS, 256>>>(Vb, g_l, b_l);

    // head_scores softmax over sequence axis
    dsoftmax_kernel<<<BATCH * NH * NL, 256>>>(Db);

    // Compression
    compress_kernel<<<dim3(BATCH * NH, NCH), 256>>>(Db, Kb, Vb, pK, pV);
    reduce_kc<<<(BATCH * NL * DIMN) / 256, 256>>>(pK, pV, Kcb, Vcb);

    // LayerNorm on compressed K/V
    ln_kernel<<<BATCH * NL, 256>>>(Kcb, g_s, b_s);
    ln_kernel<<<BATCH * NL, 256>>>(Vcb, g_s, b_s);

    // Fused long-short attention (writes fp16 C for the Wo GEMM)
    attn_kernel<<<dim3(SEQ / NQ, NH, BATCH), 256>>>(Qb, Kb, Vb, Kcb, Vcb, Ch);

    // Output projection with transposed write to (s, b, DIM)
    gemm_fp16<<<dim3(8, 128), 256, GEMM_SMEM>>>(Ch, tWo, bo, out, 1024, 1.0f, 0, 1);
}